// round 16
// baseline (speedup 1.0000x reference)
#include <cuda_runtime.h>
#include <cuda_bf16.h>
#include <math.h>
#include <stdint.h>

// ---------------------------------------------------------------------------
// CAT_Attention (B=1, BLOCK=2048, CHUNK=64, DIM=1024, CAT=1024, NH=16, HD=64)
// S = 2081, W = 65, NC = 32
// Round 16: fused comp+cvt launch — comp (blocks 0-255) reads x/W_comp fp32
// directly (inline split), cvt of all 5 tensors runs in blocks 256-383 of the
// SAME kernel, overlapping cvt's bandwidth time under comp's latency stalls.
// Dense engine v4 / attention / reduce unchanged from 409.6us baseline.
// ---------------------------------------------------------------------------

#define S_LEN   2081
#define CATD    1024
#define NHEAD   16
#define CSLICES 32

typedef __nv_bfloat16 bf16;
typedef __nv_bfloat162 bf162;

// -------------------- scratch (device globals; no allocs) -------------------
__device__ float g_fxpart[CSLICES * 32 * 1024];
__device__ float g_qkv [S_LEN * 3 * CATD];
__device__ bf16  g_xhi[2048 * 1024],  g_xlo[2048 * 1024];
__device__ bf16  g_hhi[S_LEN * 1024], g_hlo[S_LEN * 1024];
__device__ bf16  g_yhi[S_LEN * 1024], g_ylo[S_LEN * 1024];
__device__ bf16  g_y2hi[S_LEN * 1024], g_y2lo[S_LEN * 1024];
__device__ bf16  g_wexphi[1024 * 1024], g_wexplo[1024 * 1024];
__device__ bf16  g_wqkvhi[1024 * 3072], g_wqkvlo[1024 * 3072];
__device__ bf16  g_wohi[1024 * 1024],   g_wolo[1024 * 1024];
__device__ bf16  g_wfinhi[1024 * 1024], g_wfinlo[1024 * 1024];

// -------------------- row maps ---------------------------------------------
__device__ __forceinline__ int amap_final(int r) {
    if (r < 63)    return r + 1;
    if (r == 2047) return 2080;
    int u = r - 63;
    return 65 + u + (u >> 6);
}

// -------------------- helpers ----------------------------------------------
__device__ __forceinline__ uint32_t smem_u32(const void* p) {
    return (uint32_t)__cvta_generic_to_shared(p);
}

__device__ __forceinline__ void cp16(uint32_t dst, const void* src) {
    asm volatile("cp.async.cg.shared.global [%0], [%1], 16;\n" :: "r"(dst), "l"(src));
}

__device__ __forceinline__ void mma16816(float* c, const uint32_t* a, const uint32_t* b) {
    asm volatile(
        "mma.sync.aligned.m16n8k16.row.col.f32.bf16.bf16.f32 "
        "{%0,%1,%2,%3}, {%4,%5,%6,%7}, {%8,%9}, {%0,%1,%2,%3};"
        : "+f"(c[0]), "+f"(c[1]), "+f"(c[2]), "+f"(c[3])
        : "r"(a[0]), "r"(a[1]), "r"(a[2]), "r"(a[3]), "r"(b[0]), "r"(b[1]));
}

__device__ __forceinline__ void ldmat4(uint32_t* r, uint32_t addr) {
    asm volatile(
        "ldmatrix.sync.aligned.m8n8.x4.shared.b16 {%0,%1,%2,%3}, [%4];"
        : "=r"(r[0]), "=r"(r[1]), "=r"(r[2]), "=r"(r[3]) : "r"(addr));
}

__device__ __forceinline__ void ldmat4t(uint32_t* r, uint32_t addr) {
    asm volatile(
        "ldmatrix.sync.aligned.m8n8.x4.trans.shared.b16 {%0,%1,%2,%3}, [%4];"
        : "=r"(r[0]), "=r"(r[1]), "=r"(r[2]), "=r"(r[3]) : "r"(addr));
}

__device__ __forceinline__ void split2(float a, float b, uint32_t& hi, uint32_t& lo) {
    bf16 h0 = __float2bfloat16(a), h1 = __float2bfloat16(b);
    bf16 l0 = __float2bfloat16(a - __bfloat162float(h0));
    bf16 l1 = __float2bfloat16(b - __bfloat162float(h1));
    bf162 hh = __halves2bfloat162(h0, h1), ll = __halves2bfloat162(l0, l1);
    hi = *(uint32_t*)&hh; lo = *(uint32_t*)&ll;
}

__device__ __forceinline__ void st_bf16pair(bf16* hi, bf16* lo, size_t idx,
                                            float v0, float v1) {
    uint32_t h, l;
    split2(v0, v1, h, l);
    *(uint32_t*)(hi + idx) = h;
    *(uint32_t*)(lo + idx) = l;
}

// ---------------------------------------------------------------------------
// GEMM engine v4: CTA tile 128x128, 4 warps (2x2), warp tile 64x64.
// (unchanged from 409.6us baseline)
// ---------------------------------------------------------------------------
#define STAGE_SZ 32768u
#define DSMEM    98304

template<int AMODE, int CMODE>
__global__ __launch_bounds__(128, 2)
void mma_gemm(const bf16* __restrict__ Agh, const bf16* __restrict__ Agl,
              const bf16* __restrict__ Bgh, const bf16* __restrict__ Bgl,
              float* __restrict__ C, bf16* __restrict__ Chi, bf16* __restrict__ Clo,
              const float* __restrict__ cosb, const float* __restrict__ sinb,
              int M, int N, int K)
{
    extern __shared__ char dsm[];
    const uint32_t sb = smem_u32(dsm);
    const int tid = threadIdx.x, lane = tid & 31, wid = tid >> 5;
    const int warp_m = wid & 1, warp_n = wid >> 1;
    const int bm = blockIdx.y * 128, bn = blockIdx.x * 128;

    size_t aoff[4];
    uint32_t a_dst[4];
    {
        const int col = tid & 3;
        const int row0 = tid >> 2;
        const uint32_t aswz = (uint32_t)((col ^ ((row0 >> 1) & 3)) << 4);
#pragma unroll
        for (int i = 0; i < 4; i++) {
            int row = row0 + i * 32;
            int gr = bm + row;
            int r = (gr < M) ? gr : 0;
            if (AMODE == 1) r = amap_final(r);
            aoff[i] = (size_t)r * K + col * 8;
            a_dst[i] = (uint32_t)(row * 64) + aswz;
        }
    }
    const int bcol = tid & 15;
    const int brow0 = tid >> 4;
    const size_t b_col = (size_t)bn + bcol * 8;
    const uint32_t bswz = (uint32_t)((bcol ^ (brow0 & 7)) << 4);
    uint32_t b_dst[4];
#pragma unroll
    for (int i = 0; i < 4; i++) b_dst[i] = (uint32_t)((brow0 + i * 8) * 256) + bswz;

    const int quad = lane >> 3, lrow = lane & 7;
    const int c2 = quad >> 1;
    const int rowLocal = (quad & 1) * 8 + lrow;
    const int swA = (rowLocal >> 1) & 3;
    const uint32_t bRowByte = (uint32_t)(rowLocal * 256);

    float acc[32][4];
#pragma unroll
    for (int i = 0; i < 32; i++)
#pragma unroll
        for (int j = 0; j < 4; j++) acc[i][j] = 0.f;

    const int NIT = K >> 5;

    auto issue = [&](int it) {
        const int k0 = it << 5;
        const uint32_t st = sb + (uint32_t)(it % 3) * STAGE_SZ;
#pragma unroll
        for (int i = 0; i < 4; i++) {
            cp16(st + a_dst[i],         Agh + aoff[i] + k0);
            cp16(st + 8192u + a_dst[i], Agl + aoff[i] + k0);
        }
#pragma unroll
        for (int i = 0; i < 4; i++) {
            size_t src = (size_t)(k0 + brow0 + i * 8) * N + b_col;
            cp16(st + 16384u + b_dst[i], Bgh + src);
            cp16(st + 24576u + b_dst[i], Bgl + src);
        }
        asm volatile("cp.async.commit_group;\n" ::: "memory");
    };

    issue(0);
    issue(1);
    for (int it = 0; it < NIT; it++) {
        if (it + 1 < NIT)
            asm volatile("cp.async.wait_group 1;\n" ::: "memory");
        else
            asm volatile("cp.async.wait_group 0;\n" ::: "memory");
        __syncthreads();
        if (it + 2 < NIT) issue(it + 2);

        const uint32_t st = sb + (uint32_t)(it % 3) * STAGE_SZ;
#pragma unroll
        for (int kk = 0; kk < 2; kk++) {
            uint32_t ah[4][4], al[4][4];
            const uint32_t achunk = (uint32_t)((((kk * 2 + c2) ^ swA)) << 4);
#pragma unroll
            for (int mf = 0; mf < 4; mf++) {
                uint32_t aaddr = st +
                    (uint32_t)((warp_m * 64 + mf * 16 + rowLocal) * 64) + achunk;
                ldmat4(ah[mf], aaddr);
                ldmat4(al[mf], aaddr + 8192u);
            }
            const uint32_t bk = st + 16384u + (uint32_t)(kk * 16 * 256) + bRowByte;
#pragma unroll
            for (int j = 0; j < 4; j++) {
                uint32_t bh[4], bl[4];
                uint32_t bchunk = (uint32_t)(((warp_n * 8 + c2 + j * 2) ^ lrow) << 4);
                ldmat4t(bh, bk + bchunk);
                ldmat4t(bl, bk + bchunk + 8192u);
#pragma unroll
                for (int h = 0; h < 2; h++)
#pragma unroll
                    for (int mf = 0; mf < 4; mf++)
                        mma16816(acc[mf * 8 + j * 2 + h], ah[mf], &bh[h * 2]);
#pragma unroll
                for (int h = 0; h < 2; h++)
#pragma unroll
                    for (int mf = 0; mf < 4; mf++)
                        mma16816(acc[mf * 8 + j * 2 + h], ah[mf], &bl[h * 2]);
#pragma unroll
                for (int h = 0; h < 2; h++)
#pragma unroll
                    for (int mf = 0; mf < 4; mf++)
                        mma16816(acc[mf * 8 + j * 2 + h], al[mf], &bh[h * 2]);
            }
        }
    }

    const int ra = lane >> 2, ka = lane & 3;
    const int colBase = bn + warp_n * 64;

    if (CMODE == 3 && colBase < 2048) {
#pragma unroll
        for (int mf = 0; mf < 4; mf++)
#pragma unroll
            for (int hh = 0; hh < 2; hh++) {
                int gr = bm + warp_m * 64 + mf * 16 + ra + hh * 8;
                if (gr >= M) continue;
                const float* cb = cosb + (size_t)gr * 64;
                const float* sn = sinb + (size_t)gr * 64;
#pragma unroll
                for (int nf = 0; nf < 4; nf++) {
                    int d = nf * 8 + ka * 2;
                    float a0 = acc[mf * 8 + nf][hh * 2];
                    float a1 = acc[mf * 8 + nf][hh * 2 + 1];
                    float b0 = acc[mf * 8 + nf + 4][hh * 2];
                    float b1 = acc[mf * 8 + nf + 4][hh * 2 + 1];
                    float o0 = a0 * cb[d]     - b0 * sn[d];
                    float o1 = a1 * cb[d + 1] - b1 * sn[d + 1];
                    float p0 = b0 * cb[d + 32] + a0 * sn[d + 32];
                    float p1 = b1 * cb[d + 33] + a1 * sn[d + 33];
                    *(float2*)&C[(size_t)gr * N + colBase + d]      = make_float2(o0, o1);
                    *(float2*)&C[(size_t)gr * N + colBase + d + 32] = make_float2(p0, p1);
                }
            }
        return;
    }

#pragma unroll
    for (int mf = 0; mf < 4; mf++)
#pragma unroll
        for (int nf = 0; nf < 8; nf++) {
            const float* c = acc[mf * 8 + nf];
            int col = colBase + nf * 8 + ka * 2;
#pragma unroll
            for (int h = 0; h < 2; h++) {
                int gr = bm + warp_m * 64 + mf * 16 + ra + h * 8;
                if (gr >= M) continue;
                float v0 = c[h * 2], v1 = c[h * 2 + 1];
                if (CMODE == 0 || CMODE == 3) {
                    *(float2*)&C[(size_t)gr * N + col] = make_float2(v0, v1);
                } else {
                    int cr = (CMODE == 1) ? ((gr >> 6) * 65 + 1 + (gr & 63)) : gr;
                    st_bf16pair(Chi, Clo, (size_t)cr * N + col, v0, v1);
                }
            }
        }
}

// ---------------------------------------------------------------------------
// FUSED comp + cvt kernel.
// Blocks 0-255: comp v6 — fx = x.reshape(32,65536) @ W_comp (split-K, 32
//   slices x 8 N-tiles), BOTH operands streamed as raw fp32 via cp.async and
//   split to bf16 hi/lo in smem (x inline conversion = bitwise identical to
//   the old cvt path).
// Blocks 256-383: grid-stride fp32->bf16 hi/lo conversion of x + 4 weights.
// smem layout (bytes): Wf32 3x16384 @0 | Xf32 3x4096 @49152 |
//   Ahi 2x2560 @61440 | Alo 2x2560 @66560 | Bhi 2x8704 @71680 | Blo @89088
// ---------------------------------------------------------------------------
#define C2_WF32 0u
#define C2_XF32 49152u
#define C2_AHI  61440u
#define C2_ALO  66560u
#define C2_BHI  71680u
#define C2_BLO  89088u
#define C2_SMEM 106496

__global__ __launch_bounds__(256, 2)
void fused_comp_cvt(const float* __restrict__ x, const float* __restrict__ Wc,
                    float* __restrict__ fxpart,
                    bf16* __restrict__ xhi, bf16* __restrict__ xlo,
                    const float* __restrict__ wexp, bf16* __restrict__ wexphi, bf16* __restrict__ wexplo,
                    const float* __restrict__ wqkv, bf16* __restrict__ wqkvhi, bf16* __restrict__ wqkvlo,
                    const float* __restrict__ wo,   bf16* __restrict__ wohi,   bf16* __restrict__ wolo,
                    const float* __restrict__ wfin, bf16* __restrict__ wfinhi, bf16* __restrict__ wfinlo)
{
    const int tid = threadIdx.x;

    if (blockIdx.x >= 256) {
        // ---------------- cvt part (128 CTAs, grid-stride) ----------------
        for (int g = (blockIdx.x - 256) * 256 + tid; g < 2097152; g += 128 * 256) {
            const float* src; bf16 *hi, *lo; int off;
            if (g < 524288)       { src = x;    hi = xhi;    lo = xlo;    off = g; }
            else if (g < 786432)  { src = wexp; hi = wexphi; lo = wexplo; off = g - 524288; }
            else if (g < 1572864) { src = wqkv; hi = wqkvhi; lo = wqkvlo; off = g - 786432; }
            else if (g < 1835008) { src = wo;   hi = wohi;   lo = wolo;   off = g - 1572864; }
            else                  { src = wfin; hi = wfinhi; lo = wfinlo; off = g - 1835008; }
            float4 v = ((const float4*)src)[off];
            uint2 uh, ul;
            split2(v.x, v.y, uh.x, ul.x);
            split2(v.z, v.w, uh.y, ul.y);
            *(uint2*)(hi + 4 * (size_t)off) = uh;
            *(uint2*)(lo + 4 * (size_t)off) = ul;
        }
        return;
    }

    // ---------------- comp part (256 CTAs) ----------------
    extern __shared__ char dsm[];
    const uint32_t sb = smem_u32(dsm);
    const int lane = tid & 31, warp = tid >> 5;
    const int bn = (blockIdx.x & 7) * 128;
    const int kb = (blockIdx.x >> 3) * 2048;

    const int wrow = tid >> 3, wch = tid & 7;   // W: row 0..31, col-chunk 0..7
    const int xrow = tid >> 3;                  // x: row 0..31, 16B chunk (tid&7)

    auto issue = [&](int it) {
        const int k0 = kb + it * 32;
        const uint32_t s3 = (uint32_t)(it % 3);
        const uint32_t wst = sb + C2_WF32 + s3 * 16384u;
        const float* wsrc_row = Wc + (size_t)(k0 + wrow) * 1024 + bn;
#pragma unroll
        for (int i = 0; i < 4; i++) {
            int c = wch + 8 * i;
            cp16(wst + (uint32_t)(wrow * 512 + c * 16), wsrc_row + c * 4);
        }
        cp16(sb + C2_XF32 + s3 * 4096u + (uint32_t)(tid * 16),
             x + (size_t)xrow * 65536 + k0 + wch * 4);
        asm volatile("cp.async.commit_group;\n" ::: "memory");
    };

    float acc[2][2][4];
#pragma unroll
    for (int i = 0; i < 2; i++)
#pragma unroll
        for (int j = 0; j < 2; j++)
#pragma unroll
            for (int q = 0; q < 4; q++) acc[i][j][q] = 0.f;

    const int quad = lane >> 3, lrow = lane & 7;
    const uint32_t a_off = (uint32_t)(((quad & 1) * 8 + lrow) * 80 + (quad >> 1) * 16);
    const uint32_t b_off = (uint32_t)(((quad & 1) * 8 + lrow) * 272 + (warp * 16 + (quad >> 1) * 8) * 2);

    issue(0);
    issue(1);

    for (int it = 0; it < 64; it++) {
        if (it < 62)
            asm volatile("cp.async.wait_group 1;\n" ::: "memory");
        else
            asm volatile("cp.async.wait_group 0;\n" ::: "memory");
        __syncthreads();
        if (it + 2 < 64) issue(it + 2);

        const int s2 = it & 1;
        // W fp32 -> bf16 hi/lo tiles
        const char* wbase = dsm + C2_WF32 + (uint32_t)(it % 3) * 16384u + wrow * 512;
        char* bhrow = dsm + C2_BHI + (uint32_t)s2 * 8704u + wrow * 272;
        char* blrow = dsm + C2_BLO + (uint32_t)s2 * 8704u + wrow * 272;
#pragma unroll
        for (int i = 0; i < 4; i++) {
            int c = wch + 8 * i;
            float4 v = *(const float4*)(wbase + c * 16);
            uint2 uh, ul;
            split2(v.x, v.y, uh.x, ul.x);
            split2(v.z, v.w, uh.y, ul.y);
            *(uint2*)(bhrow + c * 8) = uh;
            *(uint2*)(blrow + c * 8) = ul;
        }
        // x fp32 -> bf16 hi/lo fragment tiles (bitwise == old cvt path)
        {
            float4 v = *(const float4*)(dsm + C2_XF32 + (uint32_t)(it % 3) * 4096u + tid * 16);
            uint2 uh, ul;
            split2(v.x, v.y, uh.x, ul.x);
            split2(v.z, v.w, uh.y, ul.y);
            uint32_t adst = (uint32_t)(xrow * 80 + wch * 8);
            *(uint2*)(dsm + C2_AHI + (uint32_t)s2 * 2560u + adst) = uh;
            *(uint2*)(dsm + C2_ALO + (uint32_t)s2 * 2560u + adst) = ul;
        }
        __syncthreads();

        const uint32_t as = sb + C2_AHI + (uint32_t)s2 * 2560u;
        const uint32_t ls = sb + C2_ALO + (uint32_t)s2 * 2560u;
        const uint32_t bs = sb + C2_BHI + (uint32_t)s2 * 8704u;
        const uint32_t cs = sb + C2_BLO + (uint32_t)s2 * 8704u;
#pragma unroll
        for (int kk = 0; kk < 2; kk++) {
            uint32_t ah[2][4], al[2][4], bh[4], bl[4];
#pragma unroll
            for (int mf = 0; mf < 2; mf++) {
                ldmat4(ah[mf], as + mf * 1280u + a_off + kk * 32u);
                ldmat4(al[mf], ls + mf * 1280u + a_off + kk * 32u);
            }
            ldmat4t(bh, bs + b_off + kk * 4352u);
            ldmat4t(bl, cs + b_off + kk * 4352u);
#pragma unroll
            for (int nf = 0; nf < 2; nf++)
#pragma unroll
                for (int mf = 0; mf < 2; mf++)
                    mma16816(acc[mf][nf], ah[mf], &bh[nf * 2]);
#pragma unroll
            for (int nf = 0; nf < 2; nf++)
#pragma unroll
                for (int mf = 0; mf < 2; mf++)
                    mma16816(acc[mf][nf], ah[mf], &bl[nf * 2]);
#pragma unroll
            for (int nf = 0; nf < 2; nf++)
#pragma unroll
                for (int mf = 0; mf < 2; mf++)
                    mma16816(acc[mf][nf], al[mf], &bh[nf * 2]);
        }
    }

    const int ra = lane >> 2, ka = lane & 3;
#pragma unroll
    for (int mf = 0; mf < 2; mf++)
#pragma unroll
        for (int nf = 0; nf < 2; nf++)
#pragma unroll
            for (int h = 0; h < 2; h++) {
                int row = mf * 16 + ra + h * 8;
                int col = bn + warp * 16 + nf * 8 + ka * 2;
                *(float2*)&fxpart[(size_t)((blockIdx.x >> 3) * 32 + row) * 1024 + col] =
                    make_float2(acc[mf][nf][h * 2], acc[mf][nf][h * 2 + 1]);
            }
}

// reduce partials (+bias / dummy) -> bf16 hi/lo anchor rows of h
__global__ void fx_reduce(const float* __restrict__ fxpart,
                          const float* __restrict__ dummy,
                          const float* __restrict__ bias,
                          bf16* __restrict__ hhi, bf16* __restrict__ hlo)
{
    int col = blockIdx.x * 128 + threadIdx.x;
    int c = blockIdx.y;
    float v;
    if (c == 0) {
        v = dummy[col];
    } else {
        int m = c - 1;
        float s = bias[col];
#pragma unroll 8
        for (int sl = 0; sl < CSLICES; sl++)
            s += fxpart[(size_t)(sl * 32 + m) * 1024 + col];
        v = s;
    }
    int hrow = (c < 32) ? c * 65 : 2080;
    bf16 h = __float2bfloat16(v);
    hhi[(size_t)hrow * CATD + col] = h;
    hlo[(size_t)hrow * CATD + col] = __float2bfloat16(v - __bfloat162float(h));
}

// ---------------------------------------------------------------------------
// Sparse CAT attention: K/V staged in smem; split accumulator chains.
// ---------------------------------------------------------------------------
#define KPAD 68
#define ATTN_SMEM ((97 * KPAD * 2 + 8 * 64 + 8 * 100) * 4)

__global__ __launch_bounds__(256)
void attn_kernel(const float* __restrict__ qkv,
                 bf16* __restrict__ yhi, bf16* __restrict__ ylo)
{
    extern __shared__ float dyn[];
    float* sK = dyn;
    float* sV = sK + 97 * KPAD;
    float* sq = sV + 97 * KPAD;
    float* sp = sq + 8 * 64;

    const int cq = blockIdx.x;
    const int head = blockIdx.y;
    const int tid = threadIdx.x;
    const int warp = tid >> 5, lane = tid & 31;
    const int cnt = (cq == 32) ? 1 : 65;
    const int total = cq + cnt;

    for (int idx = tid; idx < total * 16; idx += 256) {
        int kk = idx >> 4, seg = idx & 15;
        int kp = (kk < cq) ? kk * 65 : cq * 65 + (kk - cq);
        const float* base = qkv + (size_t)kp * 3072 + head * 64 + seg * 4;
        float4 kv = *(const float4*)(base + 1024);
        float4 vv = *(const float4*)(base + 2048);
        *(float4*)&sK[kk * KPAD + seg * 4] = kv;
        *(float4*)&sV[kk * KPAD + seg * 4] = vv;
    }
    __syncthreads();

    for (int j = warp; j < cnt; j += 8) {
        const int p = cq * 65 + j;
        const int nk = cq + j + 1;

        float2 q2 = *(const float2*)(qkv + (size_t)p * 3072 + head * 64 + 2 * lane);
        sq[warp * 64 + 2 * lane]     = q2.x;
        sq[warp * 64 + 2 * lane + 1] = q2.y;
        __syncwarp();

        float mx = -1e30f;
        for (int kb2 = 0; kb2 < nk; kb2 += 32) {
            int kk = kb2 + lane;
            float s = -1e30f;
            if (kk < nk) {
                float a0 = 0.f, a1 = 0.f;
#pragma unroll
                for (int d4 = 0; d4 < 16; d4 += 2) {
                    float4 qv0 = *(const float4*)&sq[warp * 64 + d4 * 4];
                    float4 kv0 = *(const float4*)&sK[kk * KPAD + d4 * 4];
                    a0 += qv0.x * kv0.x + qv0.y * kv0.y + qv0.z * kv0.z + qv0.w * kv0.w;
                    float4 qv1 = *(const float4*)&sq[warp * 64 + d4 * 4 + 4];
                    float4 kv1 = *(const float4*)&sK[kk * KPAD + d4 * 4 + 4];
                    a1 += qv1.x * kv1.x + qv1.y * kv1.y + qv1.z * kv1.z + qv1.w * kv1.w;
                }
                s = (a0 + a1) * 0.125f;
                sp[warp * 100 + kk] = s;
            }
            mx = fmaxf(mx, s);
        }
        mx = fmaxf(mx, __shfl_xor_sync(0xffffffffu, mx, 16));
        mx = fmaxf(mx, __shfl_xor_sync(0xffffffffu, mx, 8));
        mx = fmaxf(mx, __shfl_xor_sync(0xffffffffu, mx, 4));
        mx = fmaxf(mx, __shfl_xor_sync(0xffffffffu, mx, 2));
        mx = fmaxf(mx, __shfl_xor_sync(0xffffffffu, mx, 1));
        __syncwarp();

        float sum = 0.f;
        for (int kk = lane; kk < nk; kk += 32) {
            float e = __expf(sp[warp * 100 + kk] - mx);
            sp[warp * 100 + kk] = e;
            sum += e;
        }
        sum += __shfl_xor_sync(0xffffffffu, sum, 16);
        sum += __shfl_xor_sync(0xffffffffu, sum, 8);
        sum += __shfl_xor_sync(0xffffffffu, sum, 4);
        sum += __shfl_xor_sync(0xffffffffu, sum, 2);
        sum += __shfl_xor_sync(0xffffffffu, sum, 1);
        __syncwarp();
        float inv = 1.f / sum;

        float2 acc0 = make_float2(0.f, 0.f);
        float2 acc1 = make_float2(0.f, 0.f);
        int kk = 0;
        for (; kk + 1 < nk; kk += 2) {
            float pr0 = sp[warp * 100 + kk];
            float2 v0 = *(const float2*)&sV[kk * KPAD + 2 * lane];
            acc0.x += pr0 * v0.x;
            acc0.y += pr0 * v0.y;
            float pr1 = sp[warp * 100 + kk + 1];
            float2 v1 = *(const float2*)&sV[(kk + 1) * KPAD + 2 * lane];
            acc1.x += pr1 * v1.x;
            acc1.y += pr1 * v1.y;
        }
        if (kk < nk) {
            float pr = sp[warp * 100 + kk];
            float2 v2 = *(const float2*)&sV[kk * KPAD + 2 * lane];
            acc0.x += pr * v2.x;
            acc0.y += pr * v2.y;
        }
        st_bf16pair(yhi, ylo, (size_t)p * CATD + head * 64 + 2 * lane,
                    (acc0.x + acc1.x) * inv, (acc0.y + acc1.y) * inv);
        __syncwarp();
    }
}

// ---------------------------------------------------------------------------
extern "C" void kernel_launch(void* const* d_in, const int* in_sizes, int n_in,
                              void* d_out, int out_size)
{
    const float* x        = (const float*)d_in[0];
    const float* W_expand = (const float*)d_in[1];
    const float* W_comp   = (const float*)d_in[2];
    const float* b_comp   = (const float*)d_in[3];
    const float* dummy_fx = (const float*)d_in[4];
    const float* W_qkv    = (const float*)d_in[5];
    const float* W_o      = (const float*)d_in[6];
    const float* W_final  = (const float*)d_in[7];
    const float* cosb     = (const float*)d_in[8];
    const float* sinb     = (const float*)d_in[9];
    float* out = (float*)d_out;

    float *fxpart, *qkv;
    bf16 *xhi, *xlo, *hhi, *hlo, *yhi, *ylo, *y2hi, *y2lo;
    bf16 *wexphi, *wexplo, *wqkvhi, *wqkvlo, *wohi, *wolo, *wfinhi, *wfinlo;
    cudaGetSymbolAddress((void**)&fxpart, g_fxpart);
    cudaGetSymbolAddress((void**)&qkv,    g_qkv);
    cudaGetSymbolAddress((void**)&xhi,    g_xhi);
    cudaGetSymbolAddress((void**)&xlo,    g_xlo);
    cudaGetSymbolAddress((void**)&hhi,    g_hhi);
    cudaGetSymbolAddress((void**)&hlo,    g_hlo);
    cudaGetSymbolAddress((void**)&yhi,    g_yhi);
    cudaGetSymbolAddress((void**)&ylo,    g_ylo);
    cudaGetSymbolAddress((void**)&y2hi,   g_y2hi);
    cudaGetSymbolAddress((void**)&y2lo,   g_y2lo);
    cudaGetSymbolAddress((void**)&wexphi, g_wexphi);
    cudaGetSymbolAddress((void**)&wexplo, g_wexplo);
    cudaGetSymbolAddress((void**)&wqkvhi, g_wqkvhi);
    cudaGetSymbolAddress((void**)&wqkvlo, g_wqkvlo);
    cudaGetSymbolAddress((void**)&wohi,   g_wohi);
    cudaGetSymbolAddress((void**)&wolo,   g_wolo);
    cudaGetSymbolAddress((void**)&wfinhi, g_wfinhi);
    cudaGetSymbolAddress((void**)&wfinlo, g_wfinlo);

    cudaFuncSetAttribute((const void*)mma_gemm<0, 1>, cudaFuncAttributeMaxDynamicSharedMemorySize, DSMEM);
    cudaFuncSetAttribute((const void*)mma_gemm<0, 3>, cudaFuncAttributeMaxDynamicSharedMemorySize, DSMEM);
    cudaFuncSetAttribute((const void*)mma_gemm<0, 2>, cudaFuncAttributeMaxDynamicSharedMemorySize, DSMEM);
    cudaFuncSetAttribute((const void*)mma_gemm<1, 0>, cudaFuncAttributeMaxDynamicSharedMemorySize, DSMEM);
    cudaFuncSetAttribute(fused_comp_cvt, cudaFuncAttributeMaxDynamicSharedMemorySize, C2_SMEM);
    cudaFuncSetAttribute(attn_kernel, cudaFuncAttributeMaxDynamicSharedMemorySize, ATTN_SMEM);

    // launch 0: FUSED — comp split-K (blocks 0-255) + cvt of all tensors
    //           (blocks 256-383), overlapping cvt under comp's latency.
    fused_comp_cvt<<<384, 256, C2_SMEM>>>(x, W_comp, fxpart,
                                          xhi, xlo,
                                          W_expand, wexphi, wexplo,
                                          W_qkv,    wqkvhi, wqkvlo,
                                          W_o,      wohi,   wolo,
                                          W_final,  wfinhi, wfinlo);

    // launch 1: reduce partials -> bf16 anchor rows of h
    fx_reduce<<<dim3(8, 33), 128>>>(fxpart, dummy_fx, b_comp, hhi, hlo);

    // launch 2: xe = x @ W_expand -> scattered bf16 rows of h
    mma_gemm<0, 1><<<dim3(8, 16), 128, DSMEM>>>(xhi, xlo, wexphi, wexplo,
                                                nullptr, hhi, hlo, nullptr, nullptr,
                                                2048, 1024, 1024);

    // launch 3: qkv = h @ W_qkv (fp32 out, RoPE fused for q/k)
    mma_gemm<0, 3><<<dim3(24, 17), 128, DSMEM>>>(hhi, hlo, wqkvhi, wqkvlo,
                                                 qkv, nullptr, nullptr, cosb, sinb,
                                                 S_LEN, 3072, 1024);

    // launch 4: sparse CAT attention -> bf16 y
    attn_kernel<<<dim3(33, 16), 256, ATTN_SMEM>>>(qkv, yhi, ylo);

    // launch 5: y2 = y @ W_o (bf16 out)
    mma_gemm<0, 2><<<dim3(8, 17), 128, DSMEM>>>(yhi, ylo, wohi, wolo,
                                                nullptr, y2hi, y2lo, nullptr, nullptr,
                                                S_LEN, 1024, 1024);

    // launch 6: out = gather(y2) @ W_final (fp32 out)
    mma_gemm<1, 0><<<dim3(8, 16), 128, DSMEM>>>(y2hi, y2lo, wfinhi, wfinlo,
                                                out, nullptr, nullptr, nullptr, nullptr,
                                                2048, 1024, 1024);
}

// round 17
// speedup vs baseline: 1.0698x; 1.0698x over previous
#include <cuda_runtime.h>
#include <cuda_bf16.h>
#include <math.h>
#include <stdint.h>

// ---------------------------------------------------------------------------
// CAT_Attention (B=1, BLOCK=2048, CHUNK=64, DIM=1024, CAT=1024, NH=16, HD=64)
// S = 2081, W = 65, NC = 32
// Round 17: revert to round-15 baseline (409.6us, measured twice) + cvt_all
// v2 (4 independent float4 per thread, MLP=4). Everything else unchanged.
// ---------------------------------------------------------------------------

#define S_LEN   2081
#define CATD    1024
#define NHEAD   16
#define CSLICES 32

typedef __nv_bfloat16 bf16;
typedef __nv_bfloat162 bf162;

// -------------------- scratch (device globals; no allocs) -------------------
__device__ float g_fxpart[CSLICES * 32 * 1024];
__device__ float g_qkv [S_LEN * 3 * CATD];
__device__ bf16  g_xhi[2048 * 1024],  g_xlo[2048 * 1024];
__device__ bf16  g_hhi[S_LEN * 1024], g_hlo[S_LEN * 1024];
__device__ bf16  g_yhi[S_LEN * 1024], g_ylo[S_LEN * 1024];
__device__ bf16  g_y2hi[S_LEN * 1024], g_y2lo[S_LEN * 1024];
__device__ bf16  g_wexphi[1024 * 1024], g_wexplo[1024 * 1024];
__device__ bf16  g_wqkvhi[1024 * 3072], g_wqkvlo[1024 * 3072];
__device__ bf16  g_wohi[1024 * 1024],   g_wolo[1024 * 1024];
__device__ bf16  g_wfinhi[1024 * 1024], g_wfinlo[1024 * 1024];

// -------------------- row maps ---------------------------------------------
__device__ __forceinline__ int amap_final(int r) {
    if (r < 63)    return r + 1;
    if (r == 2047) return 2080;
    int u = r - 63;
    return 65 + u + (u >> 6);
}

// -------------------- helpers ----------------------------------------------
__device__ __forceinline__ uint32_t smem_u32(const void* p) {
    return (uint32_t)__cvta_generic_to_shared(p);
}

__device__ __forceinline__ void cp16(uint32_t dst, const void* src) {
    asm volatile("cp.async.cg.shared.global [%0], [%1], 16;\n" :: "r"(dst), "l"(src));
}

__device__ __forceinline__ void mma16816(float* c, const uint32_t* a, const uint32_t* b) {
    asm volatile(
        "mma.sync.aligned.m16n8k16.row.col.f32.bf16.bf16.f32 "
        "{%0,%1,%2,%3}, {%4,%5,%6,%7}, {%8,%9}, {%0,%1,%2,%3};"
        : "+f"(c[0]), "+f"(c[1]), "+f"(c[2]), "+f"(c[3])
        : "r"(a[0]), "r"(a[1]), "r"(a[2]), "r"(a[3]), "r"(b[0]), "r"(b[1]));
}

__device__ __forceinline__ void ldmat4(uint32_t* r, uint32_t addr) {
    asm volatile(
        "ldmatrix.sync.aligned.m8n8.x4.shared.b16 {%0,%1,%2,%3}, [%4];"
        : "=r"(r[0]), "=r"(r[1]), "=r"(r[2]), "=r"(r[3]) : "r"(addr));
}

__device__ __forceinline__ void ldmat4t(uint32_t* r, uint32_t addr) {
    asm volatile(
        "ldmatrix.sync.aligned.m8n8.x4.trans.shared.b16 {%0,%1,%2,%3}, [%4];"
        : "=r"(r[0]), "=r"(r[1]), "=r"(r[2]), "=r"(r[3]) : "r"(addr));
}

__device__ __forceinline__ void split2(float a, float b, uint32_t& hi, uint32_t& lo) {
    bf16 h0 = __float2bfloat16(a), h1 = __float2bfloat16(b);
    bf16 l0 = __float2bfloat16(a - __bfloat162float(h0));
    bf16 l1 = __float2bfloat16(b - __bfloat162float(h1));
    bf162 hh = __halves2bfloat162(h0, h1), ll = __halves2bfloat162(l0, l1);
    hi = *(uint32_t*)&hh; lo = *(uint32_t*)&ll;
}

__device__ __forceinline__ void st_bf16pair(bf16* hi, bf16* lo, size_t idx,
                                            float v0, float v1) {
    uint32_t h, l;
    split2(v0, v1, h, l);
    *(uint32_t*)(hi + idx) = h;
    *(uint32_t*)(lo + idx) = l;
}

// ---------------------------------------------------------------------------
// merged convert v2: all 5 tensors; 4 INDEPENDENT float4 per thread (MLP=4).
// Block b covers float4 range [b*1024, (b+1)*1024); all tensor boundaries
// are multiples of 1024 float4s, so each block touches exactly one tensor.
// ---------------------------------------------------------------------------
__global__ __launch_bounds__(256)
void cvt_all(const float* __restrict__ s0, bf16* __restrict__ h0, bf16* __restrict__ l0,
             const float* __restrict__ s1, bf16* __restrict__ h1, bf16* __restrict__ l1,
             const float* __restrict__ s2, bf16* __restrict__ h2, bf16* __restrict__ l2,
             const float* __restrict__ s3, bf16* __restrict__ h3, bf16* __restrict__ l3,
             const float* __restrict__ s4, bf16* __restrict__ h4, bf16* __restrict__ l4)
{
    int b = blockIdx.x;
    const float* src; bf16 *hi, *lo; int base;
    if (b < 512)       { src = s0; hi = h0; lo = l0; base = b; }
    else if (b < 768)  { src = s1; hi = h1; lo = l1; base = b - 512; }
    else if (b < 1536) { src = s2; hi = h2; lo = l2; base = b - 768; }
    else if (b < 1792) { src = s3; hi = h3; lo = l3; base = b - 1536; }
    else               { src = s4; hi = h4; lo = l4; base = b - 1792; }

    int i0 = base * 1024 + threadIdx.x;
    float4 v[4];
#pragma unroll
    for (int p = 0; p < 4; p++) v[p] = ((const float4*)src)[i0 + p * 256];
#pragma unroll
    for (int p = 0; p < 4; p++) {
        int i = i0 + p * 256;
        uint2 uh, ul;
        split2(v[p].x, v[p].y, uh.x, ul.x);
        split2(v[p].z, v[p].w, uh.y, ul.y);
        *(uint2*)(hi + 4 * (size_t)i) = uh;
        *(uint2*)(lo + 4 * (size_t)i) = ul;
    }
}

// ---------------------------------------------------------------------------
// GEMM engine v4: CTA tile 128x128, 4 warps (2x2), warp tile 64x64.
// ---------------------------------------------------------------------------
#define STAGE_SZ 32768u
#define DSMEM    98304

template<int AMODE, int CMODE>
__global__ __launch_bounds__(128, 2)
void mma_gemm(const bf16* __restrict__ Agh, const bf16* __restrict__ Agl,
              const bf16* __restrict__ Bgh, const bf16* __restrict__ Bgl,
              float* __restrict__ C, bf16* __restrict__ Chi, bf16* __restrict__ Clo,
              const float* __restrict__ cosb, const float* __restrict__ sinb,
              int M, int N, int K)
{
    extern __shared__ char dsm[];
    const uint32_t sb = smem_u32(dsm);
    const int tid = threadIdx.x, lane = tid & 31, wid = tid >> 5;
    const int warp_m = wid & 1, warp_n = wid >> 1;
    const int bm = blockIdx.y * 128, bn = blockIdx.x * 128;

    size_t aoff[4];
    uint32_t a_dst[4];
    {
        const int col = tid & 3;
        const int row0 = tid >> 2;
        const uint32_t aswz = (uint32_t)((col ^ ((row0 >> 1) & 3)) << 4);
#pragma unroll
        for (int i = 0; i < 4; i++) {
            int row = row0 + i * 32;
            int gr = bm + row;
            int r = (gr < M) ? gr : 0;
            if (AMODE == 1) r = amap_final(r);
            aoff[i] = (size_t)r * K + col * 8;
            a_dst[i] = (uint32_t)(row * 64) + aswz;
        }
    }
    const int bcol = tid & 15;
    const int brow0 = tid >> 4;
    const size_t b_col = (size_t)bn + bcol * 8;
    const uint32_t bswz = (uint32_t)((bcol ^ (brow0 & 7)) << 4);
    uint32_t b_dst[4];
#pragma unroll
    for (int i = 0; i < 4; i++) b_dst[i] = (uint32_t)((brow0 + i * 8) * 256) + bswz;

    const int quad = lane >> 3, lrow = lane & 7;
    const int c2 = quad >> 1;
    const int rowLocal = (quad & 1) * 8 + lrow;
    const int swA = (rowLocal >> 1) & 3;
    const uint32_t bRowByte = (uint32_t)(rowLocal * 256);

    float acc[32][4];
#pragma unroll
    for (int i = 0; i < 32; i++)
#pragma unroll
        for (int j = 0; j < 4; j++) acc[i][j] = 0.f;

    const int NIT = K >> 5;

    auto issue = [&](int it) {
        const int k0 = it << 5;
        const uint32_t st = sb + (uint32_t)(it % 3) * STAGE_SZ;
#pragma unroll
        for (int i = 0; i < 4; i++) {
            cp16(st + a_dst[i],         Agh + aoff[i] + k0);
            cp16(st + 8192u + a_dst[i], Agl + aoff[i] + k0);
        }
#pragma unroll
        for (int i = 0; i < 4; i++) {
            size_t src = (size_t)(k0 + brow0 + i * 8) * N + b_col;
            cp16(st + 16384u + b_dst[i], Bgh + src);
            cp16(st + 24576u + b_dst[i], Bgl + src);
        }
        asm volatile("cp.async.commit_group;\n" ::: "memory");
    };

    issue(0);
    issue(1);
    for (int it = 0; it < NIT; it++) {
        if (it + 1 < NIT)
            asm volatile("cp.async.wait_group 1;\n" ::: "memory");
        else
            asm volatile("cp.async.wait_group 0;\n" ::: "memory");
        __syncthreads();
        if (it + 2 < NIT) issue(it + 2);

        const uint32_t st = sb + (uint32_t)(it % 3) * STAGE_SZ;
#pragma unroll
        for (int kk = 0; kk < 2; kk++) {
            uint32_t ah[4][4], al[4][4];
            const uint32_t achunk = (uint32_t)((((kk * 2 + c2) ^ swA)) << 4);
#pragma unroll
            for (int mf = 0; mf < 4; mf++) {
                uint32_t aaddr = st +
                    (uint32_t)((warp_m * 64 + mf * 16 + rowLocal) * 64) + achunk;
                ldmat4(ah[mf], aaddr);
                ldmat4(al[mf], aaddr + 8192u);
            }
            const uint32_t bk = st + 16384u + (uint32_t)(kk * 16 * 256) + bRowByte;
#pragma unroll
            for (int j = 0; j < 4; j++) {
                uint32_t bh[4], bl[4];
                uint32_t bchunk = (uint32_t)(((warp_n * 8 + c2 + j * 2) ^ lrow) << 4);
                ldmat4t(bh, bk + bchunk);
                ldmat4t(bl, bk + bchunk + 8192u);
#pragma unroll
                for (int h = 0; h < 2; h++)
#pragma unroll
                    for (int mf = 0; mf < 4; mf++)
                        mma16816(acc[mf * 8 + j * 2 + h], ah[mf], &bh[h * 2]);
#pragma unroll
                for (int h = 0; h < 2; h++)
#pragma unroll
                    for (int mf = 0; mf < 4; mf++)
                        mma16816(acc[mf * 8 + j * 2 + h], ah[mf], &bl[h * 2]);
#pragma unroll
                for (int h = 0; h < 2; h++)
#pragma unroll
                    for (int mf = 0; mf < 4; mf++)
                        mma16816(acc[mf * 8 + j * 2 + h], al[mf], &bh[h * 2]);
            }
        }
    }

    const int ra = lane >> 2, ka = lane & 3;
    const int colBase = bn + warp_n * 64;

    if (CMODE == 3 && colBase < 2048) {
#pragma unroll
        for (int mf = 0; mf < 4; mf++)
#pragma unroll
            for (int hh = 0; hh < 2; hh++) {
                int gr = bm + warp_m * 64 + mf * 16 + ra + hh * 8;
                if (gr >= M) continue;
                const float* cb = cosb + (size_t)gr * 64;
                const float* sn = sinb + (size_t)gr * 64;
#pragma unroll
                for (int nf = 0; nf < 4; nf++) {
                    int d = nf * 8 + ka * 2;
                    float a0 = acc[mf * 8 + nf][hh * 2];
                    float a1 = acc[mf * 8 + nf][hh * 2 + 1];
                    float b0 = acc[mf * 8 + nf + 4][hh * 2];
                    float b1 = acc[mf * 8 + nf + 4][hh * 2 + 1];
                    float o0 = a0 * cb[d]     - b0 * sn[d];
                    float o1 = a1 * cb[d + 1] - b1 * sn[d + 1];
                    float p0 = b0 * cb[d + 32] + a0 * sn[d + 32];
                    float p1 = b1 * cb[d + 33] + a1 * sn[d + 33];
                    *(float2*)&C[(size_t)gr * N + colBase + d]      = make_float2(o0, o1);
                    *(float2*)&C[(size_t)gr * N + colBase + d + 32] = make_float2(p0, p1);
                }
            }
        return;
    }

#pragma unroll
    for (int mf = 0; mf < 4; mf++)
#pragma unroll
        for (int nf = 0; nf < 8; nf++) {
            const float* c = acc[mf * 8 + nf];
            int col = colBase + nf * 8 + ka * 2;
#pragma unroll
            for (int h = 0; h < 2; h++) {
                int gr = bm + warp_m * 64 + mf * 16 + ra + h * 8;
                if (gr >= M) continue;
                float v0 = c[h * 2], v1 = c[h * 2 + 1];
                if (CMODE == 0 || CMODE == 3) {
                    *(float2*)&C[(size_t)gr * N + col] = make_float2(v0, v1);
                } else {
                    int cr = (CMODE == 1) ? ((gr >> 6) * 65 + 1 + (gr & 63)) : gr;
                    st_bf16pair(Chi, Clo, (size_t)cr * N + col, v0, v1);
                }
            }
        }
}

// ---------------------------------------------------------------------------
// comp GEMM v5.1: fx = x.reshape(32,65536) @ W_comp, split-K.
// 32 slices x 8 N-tiles = 256 CTAs (single wave at 2 CTAs/SM), 64 iters each.
// ---------------------------------------------------------------------------
#define CMP_WF32  0u
#define CMP_AHI   49152u
#define CMP_ALO   56832u
#define CMP_BHI   64512u
#define CMP_BLO   81920u
#define CMP_SMEM  99328

__global__ __launch_bounds__(256, 2)
void comp_kernel(const bf16* __restrict__ xhi, const bf16* __restrict__ xlo,
                 const float* __restrict__ Wc, float* __restrict__ fxpart)
{
    extern __shared__ char dsm[];
    const uint32_t sb = smem_u32(dsm);
    const int tid = threadIdx.x, lane = tid & 31, warp = tid >> 5;
    const int bn = blockIdx.x * 128;
    const int kb = blockIdx.y * 2048;

    const int wrow = tid >> 3, wch = tid & 7;
    const int xrow = (tid & 127) >> 2, xch = tid & 3;
    const bf16* xsrc = (tid < 128) ? xhi : xlo;
    const uint32_t xdstbase = (tid < 128) ? CMP_AHI : CMP_ALO;

    auto issue = [&](int it) {
        const int k0 = kb + it * 32;
        const uint32_t s3 = (uint32_t)(it % 3);
        const uint32_t wst = sb + CMP_WF32 + s3 * 16384u;
        const float* wsrc_row = Wc + (size_t)(k0 + wrow) * 1024 + bn;
#pragma unroll
        for (int i = 0; i < 4; i++) {
            int c = wch + 8 * i;
            cp16(wst + (uint32_t)(wrow * 512 + c * 16), wsrc_row + c * 4);
        }
        cp16(sb + xdstbase + s3 * 2560u + (uint32_t)(xrow * 80 + xch * 16),
             xsrc + (size_t)xrow * 65536 + k0 + xch * 8);
        asm volatile("cp.async.commit_group;\n" ::: "memory");
    };

    float acc[2][2][4];
#pragma unroll
    for (int i = 0; i < 2; i++)
#pragma unroll
        for (int j = 0; j < 2; j++)
#pragma unroll
            for (int q = 0; q < 4; q++) acc[i][j][q] = 0.f;

    const int quad = lane >> 3, lrow = lane & 7;
    const uint32_t a_off = (uint32_t)(((quad & 1) * 8 + lrow) * 80 + (quad >> 1) * 16);
    const uint32_t b_off = (uint32_t)(((quad & 1) * 8 + lrow) * 272 + (warp * 16 + (quad >> 1) * 8) * 2);

    issue(0);
    issue(1);

    for (int it = 0; it < 64; it++) {
        if (it < 62)
            asm volatile("cp.async.wait_group 1;\n" ::: "memory");
        else
            asm volatile("cp.async.wait_group 0;\n" ::: "memory");
        __syncthreads();
        if (it + 2 < 64) issue(it + 2);

        const int s2 = it & 1;
        const char* wbase = dsm + CMP_WF32 + (uint32_t)(it % 3) * 16384u + wrow * 512;
        char* bhrow = dsm + CMP_BHI + (uint32_t)s2 * 8704u + wrow * 272;
        char* blrow = dsm + CMP_BLO + (uint32_t)s2 * 8704u + wrow * 272;
#pragma unroll
        for (int i = 0; i < 4; i++) {
            int c = wch + 8 * i;
            float4 v = *(const float4*)(wbase + c * 16);
            uint2 uh, ul;
            split2(v.x, v.y, uh.x, ul.x);
            split2(v.z, v.w, uh.y, ul.y);
            *(uint2*)(bhrow + c * 8) = uh;
            *(uint2*)(blrow + c * 8) = ul;
        }
        __syncthreads();

        const uint32_t as = sb + CMP_AHI + (uint32_t)(it % 3) * 2560u;
        const uint32_t ls = sb + CMP_ALO + (uint32_t)(it % 3) * 2560u;
        const uint32_t bs = sb + CMP_BHI + (uint32_t)s2 * 8704u;
        const uint32_t cs = sb + CMP_BLO + (uint32_t)s2 * 8704u;
#pragma unroll
        for (int kk = 0; kk < 2; kk++) {
            uint32_t ah[2][4], al[2][4], bh[4], bl[4];
#pragma unroll
            for (int mf = 0; mf < 2; mf++) {
                ldmat4(ah[mf], as + mf * 1280u + a_off + kk * 32u);
                ldmat4(al[mf], ls + mf * 1280u + a_off + kk * 32u);
            }
            ldmat4t(bh, bs + b_off + kk * 4352u);
            ldmat4t(bl, cs + b_off + kk * 4352u);
#pragma unroll
            for (int nf = 0; nf < 2; nf++)
#pragma unroll
                for (int mf = 0; mf < 2; mf++)
                    mma16816(acc[mf][nf], ah[mf], &bh[nf * 2]);
#pragma unroll
            for (int nf = 0; nf < 2; nf++)
#pragma unroll
                for (int mf = 0; mf < 2; mf++)
                    mma16816(acc[mf][nf], ah[mf], &bl[nf * 2]);
#pragma unroll
            for (int nf = 0; nf < 2; nf++)
#pragma unroll
                for (int mf = 0; mf < 2; mf++)
                    mma16816(acc[mf][nf], al[mf], &bh[nf * 2]);
        }
    }

    const int ra = lane >> 2, ka = lane & 3;
#pragma unroll
    for (int mf = 0; mf < 2; mf++)
#pragma unroll
        for (int nf = 0; nf < 2; nf++)
#pragma unroll
            for (int h = 0; h < 2; h++) {
                int row = mf * 16 + ra + h * 8;
                int col = bn + warp * 16 + nf * 8 + ka * 2;
                *(float2*)&fxpart[(size_t)(blockIdx.y * 32 + row) * 1024 + col] =
                    make_float2(acc[mf][nf][h * 2], acc[mf][nf][h * 2 + 1]);
            }
}

// reduce partials (+bias / dummy) -> bf16 hi/lo anchor rows of h
__global__ void fx_reduce(const float* __restrict__ fxpart,
                          const float* __restrict__ dummy,
                          const float* __restrict__ bias,
                          bf16* __restrict__ hhi, bf16* __restrict__ hlo)
{
    int col = blockIdx.x * 128 + threadIdx.x;
    int c = blockIdx.y;
    float v;
    if (c == 0) {
        v = dummy[col];
    } else {
        int m = c - 1;
        float s = bias[col];
#pragma unroll 8
        for (int sl = 0; sl < CSLICES; sl++)
            s += fxpart[(size_t)(sl * 32 + m) * 1024 + col];
        v = s;
    }
    int hrow = (c < 32) ? c * 65 : 2080;
    bf16 h = __float2bfloat16(v);
    hhi[(size_t)hrow * CATD + col] = h;
    hlo[(size_t)hrow * CATD + col] = __float2bfloat16(v - __bfloat162float(h));
}

// ---------------------------------------------------------------------------
// Sparse CAT attention: K/V staged in smem; split accumulator chains.
// ---------------------------------------------------------------------------
#define KPAD 68
#define ATTN_SMEM ((97 * KPAD * 2 + 8 * 64 + 8 * 100) * 4)

__global__ __launch_bounds__(256)
void attn_kernel(const float* __restrict__ qkv,
                 bf16* __restrict__ yhi, bf16* __restrict__ ylo)
{
    extern __shared__ float dyn[];
    float* sK = dyn;
    float* sV = sK + 97 * KPAD;
    float* sq = sV + 97 * KPAD;
    float* sp = sq + 8 * 64;

    const int cq = blockIdx.x;
    const int head = blockIdx.y;
    const int tid = threadIdx.x;
    const int warp = tid >> 5, lane = tid & 31;
    const int cnt = (cq == 32) ? 1 : 65;
    const int total = cq + cnt;

    for (int idx = tid; idx < total * 16; idx += 256) {
        int kk = idx >> 4, seg = idx & 15;
        int kp = (kk < cq) ? kk * 65 : cq * 65 + (kk - cq);
        const float* base = qkv + (size_t)kp * 3072 + head * 64 + seg * 4;
        float4 kv = *(const float4*)(base + 1024);
        float4 vv = *(const float4*)(base + 2048);
        *(float4*)&sK[kk * KPAD + seg * 4] = kv;
        *(float4*)&sV[kk * KPAD + seg * 4] = vv;
    }
    __syncthreads();

    for (int j = warp; j < cnt; j += 8) {
        const int p = cq * 65 + j;
        const int nk = cq + j + 1;

        float2 q2 = *(const float2*)(qkv + (size_t)p * 3072 + head * 64 + 2 * lane);
        sq[warp * 64 + 2 * lane]     = q2.x;
        sq[warp * 64 + 2 * lane + 1] = q2.y;
        __syncwarp();

        float mx = -1e30f;
        for (int kb2 = 0; kb2 < nk; kb2 += 32) {
            int kk = kb2 + lane;
            float s = -1e30f;
            if (kk < nk) {
                float a0 = 0.f, a1 = 0.f;
#pragma unroll
                for (int d4 = 0; d4 < 16; d4 += 2) {
                    float4 qv0 = *(const float4*)&sq[warp * 64 + d4 * 4];
                    float4 kv0 = *(const float4*)&sK[kk * KPAD + d4 * 4];
                    a0 += qv0.x * kv0.x + qv0.y * kv0.y + qv0.z * kv0.z + qv0.w * kv0.w;
                    float4 qv1 = *(const float4*)&sq[warp * 64 + d4 * 4 + 4];
                    float4 kv1 = *(const float4*)&sK[kk * KPAD + d4 * 4 + 4];
                    a1 += qv1.x * kv1.x + qv1.y * kv1.y + qv1.z * kv1.z + qv1.w * kv1.w;
                }
                s = (a0 + a1) * 0.125f;
                sp[warp * 100 + kk] = s;
            }
            mx = fmaxf(mx, s);
        }
        mx = fmaxf(mx, __shfl_xor_sync(0xffffffffu, mx, 16));
        mx = fmaxf(mx, __shfl_xor_sync(0xffffffffu, mx, 8));
        mx = fmaxf(mx, __shfl_xor_sync(0xffffffffu, mx, 4));
        mx = fmaxf(mx, __shfl_xor_sync(0xffffffffu, mx, 2));
        mx = fmaxf(mx, __shfl_xor_sync(0xffffffffu, mx, 1));
        __syncwarp();

        float sum = 0.f;
        for (int kk = lane; kk < nk; kk += 32) {
            float e = __expf(sp[warp * 100 + kk] - mx);
            sp[warp * 100 + kk] = e;
            sum += e;
        }
        sum += __shfl_xor_sync(0xffffffffu, sum, 16);
        sum += __shfl_xor_sync(0xffffffffu, sum, 8);
        sum += __shfl_xor_sync(0xffffffffu, sum, 4);
        sum += __shfl_xor_sync(0xffffffffu, sum, 2);
        sum += __shfl_xor_sync(0xffffffffu, sum, 1);
        __syncwarp();
        float inv = 1.f / sum;

        float2 acc0 = make_float2(0.f, 0.f);
        float2 acc1 = make_float2(0.f, 0.f);
        int kk = 0;
        for (; kk + 1 < nk; kk += 2) {
            float pr0 = sp[warp * 100 + kk];
            float2 v0 = *(const float2*)&sV[kk * KPAD + 2 * lane];
            acc0.x += pr0 * v0.x;
            acc0.y += pr0 * v0.y;
            float pr1 = sp[warp * 100 + kk + 1];
            float2 v1 = *(const float2*)&sV[(kk + 1) * KPAD + 2 * lane];
            acc1.x += pr1 * v1.x;
            acc1.y += pr1 * v1.y;
        }
        if (kk < nk) {
            float pr = sp[warp * 100 + kk];
            float2 v2 = *(const float2*)&sV[kk * KPAD + 2 * lane];
            acc0.x += pr * v2.x;
            acc0.y += pr * v2.y;
        }
        st_bf16pair(yhi, ylo, (size_t)p * CATD + head * 64 + 2 * lane,
                    (acc0.x + acc1.x) * inv, (acc0.y + acc1.y) * inv);
        __syncwarp();
    }
}

// ---------------------------------------------------------------------------
extern "C" void kernel_launch(void* const* d_in, const int* in_sizes, int n_in,
                              void* d_out, int out_size)
{
    const float* x        = (const float*)d_in[0];
    const float* W_expand = (const float*)d_in[1];
    const float* W_comp   = (const float*)d_in[2];
    const float* b_comp   = (const float*)d_in[3];
    const float* dummy_fx = (const float*)d_in[4];
    const float* W_qkv    = (const float*)d_in[5];
    const float* W_o      = (const float*)d_in[6];
    const float* W_final  = (const float*)d_in[7];
    const float* cosb     = (const float*)d_in[8];
    const float* sinb     = (const float*)d_in[9];
    float* out = (float*)d_out;

    float *fxpart, *qkv;
    bf16 *xhi, *xlo, *hhi, *hlo, *yhi, *ylo, *y2hi, *y2lo;
    bf16 *wexphi, *wexplo, *wqkvhi, *wqkvlo, *wohi, *wolo, *wfinhi, *wfinlo;
    cudaGetSymbolAddress((void**)&fxpart, g_fxpart);
    cudaGetSymbolAddress((void**)&qkv,    g_qkv);
    cudaGetSymbolAddress((void**)&xhi,    g_xhi);
    cudaGetSymbolAddress((void**)&xlo,    g_xlo);
    cudaGetSymbolAddress((void**)&hhi,    g_hhi);
    cudaGetSymbolAddress((void**)&hlo,    g_hlo);
    cudaGetSymbolAddress((void**)&yhi,    g_yhi);
    cudaGetSymbolAddress((void**)&ylo,    g_ylo);
    cudaGetSymbolAddress((void**)&y2hi,   g_y2hi);
    cudaGetSymbolAddress((void**)&y2lo,   g_y2lo);
    cudaGetSymbolAddress((void**)&wexphi, g_wexphi);
    cudaGetSymbolAddress((void**)&wexplo, g_wexplo);
    cudaGetSymbolAddress((void**)&wqkvhi, g_wqkvhi);
    cudaGetSymbolAddress((void**)&wqkvlo, g_wqkvlo);
    cudaGetSymbolAddress((void**)&wohi,   g_wohi);
    cudaGetSymbolAddress((void**)&wolo,   g_wolo);
    cudaGetSymbolAddress((void**)&wfinhi, g_wfinhi);
    cudaGetSymbolAddress((void**)&wfinlo, g_wfinlo);

    cudaFuncSetAttribute((const void*)mma_gemm<0, 1>, cudaFuncAttributeMaxDynamicSharedMemorySize, DSMEM);
    cudaFuncSetAttribute((const void*)mma_gemm<0, 3>, cudaFuncAttributeMaxDynamicSharedMemorySize, DSMEM);
    cudaFuncSetAttribute((const void*)mma_gemm<0, 2>, cudaFuncAttributeMaxDynamicSharedMemorySize, DSMEM);
    cudaFuncSetAttribute((const void*)mma_gemm<1, 0>, cudaFuncAttributeMaxDynamicSharedMemorySize, DSMEM);
    cudaFuncSetAttribute(comp_kernel, cudaFuncAttributeMaxDynamicSharedMemorySize, CMP_SMEM);
    cudaFuncSetAttribute(attn_kernel, cudaFuncAttributeMaxDynamicSharedMemorySize, ATTN_SMEM);

    // launch 0: all fp32 -> bf16 hi/lo conversions (MLP=4 version)
    cvt_all<<<2048, 256>>>(x,        xhi,    xlo,
                           W_expand, wexphi, wexplo,
                           W_qkv,    wqkvhi, wqkvlo,
                           W_o,      wohi,   wolo,
                           W_final,  wfinhi, wfinlo);

    // launch 1: fx partials (single-wave split-K: 256 CTAs, 64 iters)
    comp_kernel<<<dim3(8, CSLICES), 256, CMP_SMEM>>>(xhi, xlo, W_comp, fxpart);

    // launch 2: reduce partials -> bf16 anchor rows of h
    fx_reduce<<<dim3(8, 33), 128>>>(fxpart, dummy_fx, b_comp, hhi, hlo);

    // launch 3: xe = x @ W_expand -> scattered bf16 rows of h
    mma_gemm<0, 1><<<dim3(8, 16), 128, DSMEM>>>(xhi, xlo, wexphi, wexplo,
                                                nullptr, hhi, hlo, nullptr, nullptr,
                                                2048, 1024, 1024);

    // launch 4: qkv = h @ W_qkv (fp32 out, RoPE fused for q/k)
    mma_gemm<0, 3><<<dim3(24, 17), 128, DSMEM>>>(hhi, hlo, wqkvhi, wqkvlo,
                                                 qkv, nullptr, nullptr, cosb, sinb,
                                                 S_LEN, 3072, 1024);

    // launch 5: sparse CAT attention -> bf16 y
    attn_kernel<<<dim3(33, 16), 256, ATTN_SMEM>>>(qkv, yhi, ylo);

    // launch 6: y2 = y @ W_o (bf16 out)
    mma_gemm<0, 2><<<dim3(8, 17), 128, DSMEM>>>(yhi, ylo, wohi, wolo,
                                                nullptr, y2hi, y2lo, nullptr, nullptr,
                                                S_LEN, 1024, 1024);

    // launch 7: out = gather(y2) @ W_final (fp32 out)
    mma_gemm<1, 0><<<dim3(8, 16), 128, DSMEM>>>(y2hi, y2lo, wfinhi, wfinlo,
                                                out, nullptr, nullptr, nullptr, nullptr,
                                                2048, 1024, 1024);
}